// round 3
// baseline (speedup 1.0000x reference)
#include <cuda_runtime.h>

#define NN 32
#define MM 8
#define PP 16
#define BB 64
#define TT 128
#define NP1 33

// ---------------- global scratch (no cudaMalloc allowed) ----------------
__device__ float g_muf[BB][TT][NN];
__device__ float g_mup[BB][TT][NN];
__device__ float g_Sigf[BB][TT][NN][NN];
__device__ float g_Sigp[BB][TT][NN][NN];
__device__ float g_J[BB][TT][NN][NN];    // t in [0, TT-2]
__device__ float g_G[BB][TT][NN][NN];    // Gs_t = sym(Sigf_t - J Sigp_{t+1} J^T)
__device__ float g_mb[BB][TT][NN];       // mb_t = muf_t - J mup_{t+1}

// ================= forward filter: 1 CTA / batch, 512 threads =================
__global__ void __launch_bounds__(512) fwd_kernel(
    const float* __restrict__ Y, const float* __restrict__ U,
    const float* __restrict__ A, const float* __restrict__ Bm,
    const float* __restrict__ C, const float* __restrict__ mu0,
    const float* __restrict__ Sigma0)
{
    const int b = blockIdx.x;
    const int tid = threadIdx.x;
    const int j  = tid & 31;      // column
    const int i0 = tid >> 5;      // row pair base (== warp id), rows i0 and i0+16
    const int lane = tid & 31, wid = tid >> 5;

    __shared__ float sA[NN][NN + 1], sC[PP][NN + 1], sB[NN][MM + 1];
    __shared__ float sSig[NN][NN + 1], sTmp[NN][NN + 1], sSigp[NN][NN + 1];
    __shared__ float sH[PP][NN + 1], sCS[PP][NN + 1], sS0[PP][PP + 1], sK[NN][PP + 1];
    __shared__ float sCA[PP][NN + 1], sCCt[PP][PP + 1];
    __shared__ float smu[NN], smup[NN], sr[PP], sy[PP], su[MM];

    const float* Ab = A  + (size_t)b * TT * NN * NN;
    const float* Cb = C  + (size_t)b * TT * PP * NN;
    const float* Bb = Bm + (size_t)b * TT * NN * MM;
    const float* Yb = Y  + (size_t)b * TT * PP;
    const float* Ub = U  + (size_t)b * TT * MM;

    // init carry + t=0 inputs
    for (int idx = tid; idx < NN * NN; idx += 512) {
        sSig[idx >> 5][idx & 31] = Sigma0[idx];
        sA[idx >> 5][idx & 31]   = Ab[idx];
    }
    for (int idx = tid; idx < PP * NN; idx += 512) sC[idx >> 5][idx & 31] = Cb[idx];
    if (tid < NN * MM) sB[tid >> 3][tid & 7] = Bb[tid];
    if (tid < NN) smu[tid] = mu0[tid];
    if (tid < PP) sy[tid] = Yb[tid];
    else if (tid < PP + MM) su[tid - PP] = Ub[tid - PP];
    __syncthreads();

    for (int t = 0; t < TT; ++t) {
        // ---- P1: tmp = A@Sig ; CA = C@A ; CCt = C@C^T ; mu_p ----
        {
            float a0 = 0.f, a1 = 0.f;
            #pragma unroll
            for (int k = 0; k < NN; ++k) {
                const float r = sSig[k][j];
                a0 += sA[i0][k] * r; a1 += sA[i0 + 16][k] * r;
            }
            sTmp[i0][j] = a0; sTmp[i0 + 16][j] = a1;
        }
        {
            float ca = 0.f;
            #pragma unroll
            for (int k = 0; k < NN; ++k) ca += sC[i0][k] * sA[k][j];
            sCA[i0][j] = ca;
        }
        if (j < PP) {
            float cc = 0.f;
            #pragma unroll
            for (int k = 0; k < NN; ++k) cc += sC[i0][k] * sC[j][k];
            sCCt[i0][j] = cc;
        }
        if (tid < NN) {
            float m = 0.f;
            #pragma unroll
            for (int k = 0; k < NN; ++k) m += sA[tid][k] * smu[k];
            #pragma unroll
            for (int k = 0; k < MM; ++k) m += sB[tid][k] * su[k];
            smup[tid] = m;
        }
        __syncthreads();

        // ---- P2: Sigp = tmp@A^T + Q ; H = C@tmp ; r = y - C mu_p ----
        {
            float a0 = 0.f, a1 = 0.f;
            #pragma unroll
            for (int k = 0; k < NN; ++k) {
                const float r = sA[j][k];
                a0 += sTmp[i0][k] * r; a1 += sTmp[i0 + 16][k] * r;
            }
            a0 += (i0 == j) ? 0.01f : 0.f;
            a1 += (i0 + 16 == j) ? 0.01f : 0.f;
            sSigp[i0][j] = a0; sSigp[i0 + 16][j] = a1;
            float* gp = &g_Sigp[b][t][0][0];
            gp[i0 * NN + j] = a0; gp[(i0 + 16) * NN + j] = a1;
        }
        {
            float h = 0.f;
            #pragma unroll
            for (int k = 0; k < NN; ++k) h += sC[i0][k] * sTmp[k][j];
            sH[i0][j] = h;
        }
        if (tid >= 32 && tid < 32 + PP) {
            const int i = tid - 32;
            float m = 0.f;
            #pragma unroll
            for (int k = 0; k < NN; ++k) m += sC[i][k] * smup[k];
            sr[i] = sy[i] - m;
        }
        __syncthreads();

        // ---- P3: CS = H@A^T + 0.01C ; S0 = H@CA^T + 0.01 CCt ----
        {
            float cs = 0.f;
            #pragma unroll
            for (int k = 0; k < NN; ++k) cs += sH[i0][k] * sA[j][k];
            sCS[i0][j] = cs + 0.01f * sC[i0][j];
        }
        if (j < PP) {
            float s0 = 0.f;
            #pragma unroll
            for (int k = 0; k < NN; ++k) s0 += sH[i0][k] * sCA[j][k];
            sS0[i0][j] = s0 + 0.01f * sCCt[i0][j];
        }
        __syncthreads();

        // ---- P4: warp0 register Gauss-Jordan on [sym(S0)+R | CS];
        //          warps 1..15 prefetch next step inputs ----
        if (wid == 0) {
            float colA[PP], colB[PP];
            #pragma unroll
            for (int i = 0; i < PP; ++i) {
                colA[i] = (lane < PP)
                    ? 0.5f * (sS0[i][lane] + sS0[lane][i]) + ((i == lane) ? 0.01f : 0.f)
                    : sCS[i][lane - PP];
                colB[i] = (lane < PP) ? sCS[i][PP + lane] : 0.f;
            }
            #pragma unroll
            for (int k = 0; k < PP; ++k) {
                float f[PP];
                #pragma unroll
                for (int i = 0; i < PP; ++i) f[i] = __shfl_sync(0xffffffffu, colA[i], k);
                const float pr = 1.0f / f[k];
                #pragma unroll
                for (int i = 0; i < PP; ++i) {
                    if (i != k) {
                        const float g = f[i] * pr;
                        colA[i] -= g * colA[k];
                        colB[i] -= g * colB[k];
                    }
                }
                colA[k] *= pr; colB[k] *= pr;
            }
            if (lane >= PP) {
                #pragma unroll
                for (int i = 0; i < PP; ++i) sK[lane - PP][i] = colA[i];
            } else {
                #pragma unroll
                for (int i = 0; i < PP; ++i) sK[PP + lane][i] = colB[i];
            }
        } else if (t + 1 < TT) {
            const int wt = tid - 32;
            const float* An = Ab + (size_t)(t + 1) * NN * NN;
            const float* Cn = Cb + (size_t)(t + 1) * PP * NN;
            const float* Bn = Bb + (size_t)(t + 1) * NN * MM;
            for (int idx = wt; idx < NN * NN; idx += 480) sA[idx >> 5][idx & 31] = An[idx];
            for (int idx = wt; idx < PP * NN; idx += 480) sC[idx >> 5][idx & 31] = Cn[idx];
            for (int idx = wt; idx < NN * MM; idx += 480) sB[idx >> 3][idx & 7] = Bn[idx];
            if (wt < PP) sy[wt] = Yb[(t + 1) * PP + wt];
            else if (wt < PP + MM) su[wt - PP] = Ub[(t + 1) * MM + (wt - PP)];
        }
        __syncthreads();

        // ---- P5 (fused): X = Sigp - K@CS; Sig_f = sym(X); mu_f ----
        {
            float x0  = sSigp[i0][j],      x1  = sSigp[i0 + 16][j];
            float xt0 = sSigp[j][i0],      xt1 = sSigp[j][i0 + 16];
            #pragma unroll
            for (int k = 0; k < PP; ++k) {
                const float c  = sCS[k][j];
                const float kj = sK[j][k];
                x0  -= sK[i0][k] * c;       x1  -= sK[i0 + 16][k] * c;
                xt0 -= kj * sCS[k][i0];     xt1 -= kj * sCS[k][i0 + 16];
            }
            const float v0 = 0.5f * (x0 + xt0);
            const float v1 = 0.5f * (x1 + xt1);
            sSig[i0][j] = v0; sSig[i0 + 16][j] = v1;
            float* gf = &g_Sigf[b][t][0][0];
            gf[i0 * NN + j] = v0; gf[(i0 + 16) * NN + j] = v1;
        }
        if (tid < NN) {
            float m = smup[tid];
            #pragma unroll
            for (int k = 0; k < PP; ++k) m += sK[tid][k] * sr[k];
            smu[tid] = m;
            g_muf[b][t][tid] = m;
            g_mup[b][t][tid] = smup[tid];
        }
        __syncthreads();
    }
}

// ===== smoother gains + backward-constants (fully parallel over b,t) =====
// J_t = Sigf_t A_t^T Sigp_{t+1}^{-1}
// Gs_t = sym(Sigf_t - J Sigp_{t+1} J^T) ;  mb_t = muf_t - J mup_{t+1}
__global__ void __launch_bounds__(256) jgain_kernel(const float* __restrict__ A)
{
    const int t = blockIdx.x;     // 0..TT-2
    const int b = blockIdx.y;
    const int tid = threadIdx.x;
    const int tx = tid & 15, ty = tid >> 4;

    __shared__ float sSf[NN][NN + 1], sA[NN][NN + 1], sX[NN][NN + 1], sT2[NN][NN + 1];
    __shared__ float prow[2][2 * NN];
    __shared__ float sf[2][NN];
    __shared__ float smp1[NN];

    const float* Ab = A + ((size_t)b * TT + t) * NN * NN;
    for (int idx = tid; idx < NN * NN; idx += 256) {
        sSf[idx >> 5][idx & 31] = g_Sigf[b][t][idx >> 5][idx & 31];
        sA[idx >> 5][idx & 31]  = Ab[idx];
    }
    if (tid < NN) smp1[tid] = g_mup[b][t + 1][tid];
    __syncthreads();

    // X = Sigf @ A^T
    {
        float a00 = 0.f, a01 = 0.f, a10 = 0.f, a11 = 0.f;
        #pragma unroll
        for (int k = 0; k < NN; ++k) {
            const float l0 = sSf[ty][k], l1 = sSf[ty + 16][k];
            const float r0 = sA[tx][k],  r1 = sA[tx + 16][k];
            a00 += l0 * r0; a01 += l0 * r1; a10 += l1 * r0; a11 += l1 * r1;
        }
        sX[ty][tx] = a00;      sX[ty][tx + 16] = a01;
        sX[ty + 16][tx] = a10; sX[ty + 16][tx + 16] = a11;
    }
    __syncthreads();

    // Gauss-Jordan on [Sigp_{t+1} | X^T]; thread owns 8 cols of one row in regs
    const int row = tid >> 3;
    const int c0  = (tid & 7) * 8;
    float r8[8];
    if (c0 < NN) {
        #pragma unroll
        for (int m = 0; m < 8; ++m) r8[m] = g_Sigp[b][t + 1][row][c0 + m];
    } else {
        #pragma unroll
        for (int m = 0; m < 8; ++m) r8[m] = sX[c0 - NN + m][row];   // X^T
    }
    #pragma unroll
    for (int k = 0; k < NN; ++k) {
        const int pb = k & 1;
        if (row == k) {
            #pragma unroll
            for (int m = 0; m < 8; ++m) prow[pb][c0 + m] = r8[m];
        }
        if ((tid & 7) == (k >> 3)) sf[pb][row] = r8[k & 7];
        __syncthreads();
        const float pr = 1.0f / prow[pb][k];
        if (row == k) {
            #pragma unroll
            for (int m = 0; m < 8; ++m) r8[m] *= pr;
        } else {
            const float g = sf[pb][row] * pr;
            #pragma unroll
            for (int m = 0; m < 8; ++m) r8[m] -= g * prow[pb][c0 + m];
        }
    }
    __syncthreads();
    // J = Z^T (Z = Sigp^{-1} X^T) -> stage into sX
    if (c0 >= NN) {
        #pragma unroll
        for (int m = 0; m < 8; ++m) sX[c0 - NN + m][row] = r8[m];
    }
    __syncthreads();
    // store J; reload Sigp into sA (reuse)
    for (int idx = tid; idx < NN * NN; idx += 256) {
        g_J[b][t][idx >> 5][idx & 31] = sX[idx >> 5][idx & 31];
        sA[idx >> 5][idx & 31] = g_Sigp[b][t + 1][idx >> 5][idx & 31];
    }
    __syncthreads();

    // T2 = J @ Sigp_{t+1}
    {
        float a00 = 0.f, a01 = 0.f, a10 = 0.f, a11 = 0.f;
        #pragma unroll
        for (int k = 0; k < NN; ++k) {
            const float l0 = sX[ty][k], l1 = sX[ty + 16][k];
            const float r0 = sA[k][tx], r1 = sA[k][tx + 16];
            a00 += l0 * r0; a01 += l0 * r1; a10 += l1 * r0; a11 += l1 * r1;
        }
        sT2[ty][tx] = a00;      sT2[ty][tx + 16] = a01;
        sT2[ty + 16][tx] = a10; sT2[ty + 16][tx + 16] = a11;
    }
    __syncthreads();

    // Gs = sym(Sf) - sym(T2 @ J^T) ; mb = muf - J mp1
    {
        float e00 = 0.f, e01 = 0.f, e10 = 0.f, e11 = 0.f;
        float f00 = 0.f, f01 = 0.f, f10 = 0.f, f11 = 0.f;
        #pragma unroll
        for (int k = 0; k < NN; ++k) {
            const float t0 = sT2[ty][k], t1 = sT2[ty + 16][k];
            const float j0 = sX[tx][k],  j1 = sX[tx + 16][k];
            e00 += t0 * j0; e01 += t0 * j1; e10 += t1 * j0; e11 += t1 * j1;
            const float tt0 = sT2[tx][k], tt1 = sT2[tx + 16][k];
            const float jy0 = sX[ty][k],  jy1 = sX[ty + 16][k];
            f00 += tt0 * jy0; f01 += tt1 * jy0; f10 += tt0 * jy1; f11 += tt1 * jy1;
        }
        float* gg = &g_G[b][t][0][0];
        gg[ty * NN + tx]             = 0.5f * (sSf[ty][tx] + sSf[tx][ty]) - 0.5f * (e00 + f00);
        gg[ty * NN + tx + 16]        = 0.5f * (sSf[ty][tx + 16] + sSf[tx + 16][ty]) - 0.5f * (e01 + f01);
        gg[(ty + 16) * NN + tx]      = 0.5f * (sSf[ty + 16][tx] + sSf[tx][ty + 16]) - 0.5f * (e10 + f10);
        gg[(ty + 16) * NN + tx + 16] = 0.5f * (sSf[ty + 16][tx + 16] + sSf[tx + 16][ty + 16]) - 0.5f * (e11 + f11);
    }
    if (tid < NN) {
        float m = g_muf[b][t][tid];
        #pragma unroll
        for (int k = 0; k < NN; ++k) m -= sX[tid][k] * smp1[k];
        g_mb[b][t][tid] = m;
    }
}

// ========== backward RTS recursion: Sig_s = Gs + sym(J Sig_s J^T) ==========
__global__ void __launch_bounds__(512) bwd_kernel(float* __restrict__ out)
{
    const int b = blockIdx.x;
    const int tid = threadIdx.x;
    const int j  = tid & 31;
    const int i0 = tid >> 5;

    __shared__ float sJ[2][NN][NN + 1], sTmp[NN][NN + 1], sSig[NN][NN + 1];
    __shared__ float smu[NN];

    // t = TT-1: smoothed == filtered
    {
        const float v0 = g_Sigf[b][TT - 1][i0][j];
        const float v1 = g_Sigf[b][TT - 1][i0 + 16][j];
        sSig[i0][j] = v0; sSig[i0 + 16][j] = v1;
        const size_t base = ((size_t)b * TT + (TT - 1)) * NN;
        out[(base + i0) * NP1 + 1 + j] = v0;
        out[(base + i0 + 16) * NP1 + 1 + j] = v1;
        if (tid < NN) {
            const float m = g_muf[b][TT - 1][tid];
            smu[tid] = m;
            out[(base + tid) * NP1] = m;
        }
    }
    // prefetch t = TT-2
    float pG0 = g_G[b][TT - 2][i0][j];
    float pG1 = g_G[b][TT - 2][i0 + 16][j];
    sJ[0][i0][j]      = g_J[b][TT - 2][i0][j];
    sJ[0][i0 + 16][j] = g_J[b][TT - 2][i0 + 16][j];
    __syncthreads();

    int cur = 0;
    for (int t = TT - 2; t >= 0; --t) {
        // phase 1: tmp = J @ Sig_s ; mu update (regs) ; prefetch t-1
        float a0 = 0.f, a1 = 0.f;
        #pragma unroll
        for (int k = 0; k < NN; ++k) {
            const float r = sSig[k][j];
            a0 += sJ[cur][i0][k] * r; a1 += sJ[cur][i0 + 16][k] * r;
        }
        sTmp[i0][j] = a0; sTmp[i0 + 16][j] = a1;

        float m = 0.f;
        if (tid < NN) {
            m = g_mb[b][t][tid];
            #pragma unroll
            for (int k = 0; k < NN; ++k) m += sJ[cur][tid][k] * smu[k];
        }
        float nJ0 = 0.f, nJ1 = 0.f, nG0 = 0.f, nG1 = 0.f;
        if (t > 0) {
            nJ0 = g_J[b][t - 1][i0][j];     nJ1 = g_J[b][t - 1][i0 + 16][j];
            nG0 = g_G[b][t - 1][i0][j];     nG1 = g_G[b][t - 1][i0 + 16][j];
        }
        __syncthreads();

        // phase 2: Sig_s = Gs + sym(tmp @ J^T) ; emit ; stage next J
        {
            float e0 = 0.f, e1 = 0.f, et0 = 0.f, et1 = 0.f;
            #pragma unroll
            for (int k = 0; k < NN; ++k) {
                const float jj = sJ[cur][j][k];
                const float tj = sTmp[j][k];
                e0  += sTmp[i0][k] * jj;      e1  += sTmp[i0 + 16][k] * jj;
                et0 += tj * sJ[cur][i0][k];   et1 += tj * sJ[cur][i0 + 16][k];
            }
            const float v0 = pG0 + 0.5f * (e0 + et0);
            const float v1 = pG1 + 0.5f * (e1 + et1);
            sSig[i0][j] = v0; sSig[i0 + 16][j] = v1;
            const size_t base = ((size_t)b * TT + t) * NN;
            out[(base + i0) * NP1 + 1 + j] = v0;
            out[(base + i0 + 16) * NP1 + 1 + j] = v1;
            if (tid < NN) {
                smu[tid] = m;
                out[(base + tid) * NP1] = m;
            }
        }
        if (t > 0) {
            sJ[cur ^ 1][i0][j] = nJ0; sJ[cur ^ 1][i0 + 16][j] = nJ1;
            pG0 = nG0; pG1 = nG1;
        }
        __syncthreads();
        cur ^= 1;
    }
}

// ---------------- launch ----------------
extern "C" void kernel_launch(void* const* d_in, const int* in_sizes, int n_in,
                              void* d_out, int out_size)
{
    const float* Y      = (const float*)d_in[0];
    const float* U      = (const float*)d_in[1];
    const float* A      = (const float*)d_in[2];
    const float* Bm     = (const float*)d_in[3];
    const float* C      = (const float*)d_in[4];
    const float* mu0    = (const float*)d_in[5];
    const float* Sigma0 = (const float*)d_in[6];
    float* out = (float*)d_out;

    fwd_kernel<<<BB, 512>>>(Y, U, A, Bm, C, mu0, Sigma0);
    jgain_kernel<<<dim3(TT - 1, BB), 256>>>(A);
    bwd_kernel<<<BB, 512>>>(out);
}

// round 4
// speedup vs baseline: 1.2185x; 1.2185x over previous
#include <cuda_runtime.h>

#define NN 32
#define MM 8
#define PP 16
#define BB 64
#define TT 128
#define NP1 33

// ---------------- global scratch ----------------
__device__ float g_muf[BB][TT][NN];
__device__ float g_mup[BB][TT][NN];
__device__ float g_Sigf[BB][TT][NN][NN];
__device__ float g_Sigp[BB][TT][NN][NN];
__device__ float g_J[BB][TT][NN][NN];    // t in [0, TT-2]
__device__ float g_G[BB][TT][NN][NN];    // Gs_t = Sigf_t - J Sigp_{t+1} J^T
__device__ float g_mb[BB][TT][NN];       // mb_t = muf_t - J mup_{t+1}

// ================= forward filter: 1 CTA / batch, 512 threads =================
// Warp-group split: g0 = warps 0-7 (big 32x32 matmuls, 2x2 tiles),
//                   g1 = warps 8-15 (16-row matmuls), running concurrently.
__global__ void __launch_bounds__(512) fwd_kernel(
    const float* __restrict__ Y, const float* __restrict__ U,
    const float* __restrict__ A, const float* __restrict__ Bm,
    const float* __restrict__ C, const float* __restrict__ mu0,
    const float* __restrict__ Sigma0)
{
    const int b = blockIdx.x;
    const int tid = threadIdx.x;
    const int lane = tid & 31, wid = tid >> 5;
    const int g  = tid >> 8;          // 0 or 1
    const int t8 = tid & 255;
    const int tx = t8 & 15;
    const int ty = t8 >> 4;           // 0..15

    __shared__ float sA[NN][NN + 1], sC[PP][NN + 1], sB[NN][MM + 1];
    __shared__ float sSig[NN][NN + 1], sTmp[NN][NN + 1], sSigp[NN][NN + 1];
    __shared__ float sH[PP][NN + 1], sCS[PP][NN + 1], sS0[PP][PP + 1], sK[NN][PP + 1];
    __shared__ float sCA[PP][NN + 1], sCCt[PP][PP + 1];
    __shared__ float smu[NN], smup[NN], sr[PP], sy[PP], su[MM];

    const float* Ab = A  + (size_t)b * TT * NN * NN;
    const float* Cb = C  + (size_t)b * TT * PP * NN;
    const float* Bb = Bm + (size_t)b * TT * NN * MM;
    const float* Yb = Y  + (size_t)b * TT * PP;
    const float* Ub = U  + (size_t)b * TT * MM;

    for (int idx = tid; idx < NN * NN; idx += 512) {
        sSig[idx >> 5][idx & 31] = Sigma0[idx];
        sA[idx >> 5][idx & 31]   = Ab[idx];
    }
    for (int idx = tid; idx < PP * NN; idx += 512) sC[idx >> 5][idx & 31] = Cb[idx];
    if (tid < NN * MM) sB[tid >> 3][tid & 7] = Bb[tid];
    if (tid < NN) smu[tid] = mu0[tid];
    if (tid < PP) sy[tid] = Yb[tid];
    else if (tid < PP + MM) su[tid - PP] = Ub[tid - PP];
    __syncthreads();

    for (int t = 0; t < TT; ++t) {
        // ==== P1: g0: tmp = A@Sig (2x2) | g1: CA = C@A, CCt = C@C^T | mup ====
        if (g == 0) {
            float a00 = 0.f, a01 = 0.f, a10 = 0.f, a11 = 0.f;
            #pragma unroll
            for (int k = 0; k < NN; ++k) {
                const float l0 = sA[ty][k],   l1 = sA[ty + 16][k];
                const float r0 = sSig[k][tx], r1 = sSig[k][tx + 16];
                a00 += l0 * r0; a01 += l0 * r1; a10 += l1 * r0; a11 += l1 * r1;
            }
            sTmp[ty][tx] = a00;      sTmp[ty][tx + 16] = a01;
            sTmp[ty + 16][tx] = a10; sTmp[ty + 16][tx + 16] = a11;
        } else {
            float ca0 = 0.f, ca1 = 0.f, cc = 0.f;
            #pragma unroll
            for (int k = 0; k < NN; ++k) {
                const float c = sC[ty][k];
                ca0 += c * sA[k][tx]; ca1 += c * sA[k][tx + 16];
                cc  += c * sC[tx][k];
            }
            sCA[ty][tx] = ca0; sCA[ty][tx + 16] = ca1;
            sCCt[ty][tx] = cc;
            if (tid >= 480) {
                const int l = tid - 480;
                float m = 0.f;
                #pragma unroll
                for (int k = 0; k < NN; ++k) m += sA[l][k] * smu[k];
                #pragma unroll
                for (int k = 0; k < MM; ++k) m += sB[l][k] * su[k];
                smup[l] = m;
            }
        }
        __syncthreads();

        // ==== P2: g0: Sigp = tmp@A^T + Q | g1: H = C@tmp | r ====
        if (g == 0) {
            float a00 = 0.f, a01 = 0.f, a10 = 0.f, a11 = 0.f;
            #pragma unroll
            for (int k = 0; k < NN; ++k) {
                const float l0 = sTmp[ty][k],  l1 = sTmp[ty + 16][k];
                const float r0 = sA[tx][k],    r1 = sA[tx + 16][k];
                a00 += l0 * r0; a01 += l0 * r1; a10 += l1 * r0; a11 += l1 * r1;
            }
            const float q = (ty == tx) ? 0.01f : 0.f;
            a00 += q; a11 += q;
            sSigp[ty][tx] = a00;      sSigp[ty][tx + 16] = a01;
            sSigp[ty + 16][tx] = a10; sSigp[ty + 16][tx + 16] = a11;
            float* gp = &g_Sigp[b][t][0][0];
            gp[ty * NN + tx] = a00;        gp[ty * NN + tx + 16] = a01;
            gp[(ty + 16) * NN + tx] = a10; gp[(ty + 16) * NN + tx + 16] = a11;
        } else {
            float h0 = 0.f, h1 = 0.f;
            #pragma unroll
            for (int k = 0; k < NN; ++k) {
                const float c = sC[ty][k];
                h0 += c * sTmp[k][tx]; h1 += c * sTmp[k][tx + 16];
            }
            sH[ty][tx] = h0; sH[ty][tx + 16] = h1;
            if (tid >= 480 && tid < 480 + PP) {
                const int i = tid - 480;
                float m = 0.f;
                #pragma unroll
                for (int k = 0; k < NN; ++k) m += sC[i][k] * smup[k];
                sr[i] = sy[i] - m;
            }
        }
        __syncthreads();

        // ==== P3: g0: CS = H@A^T + 0.01C | g1: S0 = H@CA^T + 0.01 CCt ====
        if (g == 0) {
            float cs0 = 0.f, cs1 = 0.f;
            #pragma unroll
            for (int k = 0; k < NN; ++k) {
                const float h = sH[ty][k];
                cs0 += h * sA[tx][k]; cs1 += h * sA[tx + 16][k];
            }
            sCS[ty][tx]      = cs0 + 0.01f * sC[ty][tx];
            sCS[ty][tx + 16] = cs1 + 0.01f * sC[ty][tx + 16];
        } else {
            float s0 = 0.f;
            #pragma unroll
            for (int k = 0; k < NN; ++k) s0 += sH[ty][k] * sCA[tx][k];
            sS0[ty][tx] = s0 + 0.01f * sCCt[ty][tx];
        }
        __syncthreads();

        // ==== P4: warp0 GJ on [sym(S0)+R | CS] -> K ; warps 1-15 prefetch ====
        if (wid == 0) {
            float colA[PP], colB[PP];
            #pragma unroll
            for (int i = 0; i < PP; ++i) {
                colA[i] = (lane < PP)
                    ? 0.5f * (sS0[i][lane] + sS0[lane][i]) + ((i == lane) ? 0.01f : 0.f)
                    : sCS[i][lane - PP];
                colB[i] = (lane < PP) ? sCS[i][PP + lane] : 0.f;
            }
            #pragma unroll
            for (int k = 0; k < PP; ++k) {
                float f[PP];
                #pragma unroll
                for (int i = 0; i < PP; ++i) f[i] = __shfl_sync(0xffffffffu, colA[i], k);
                const float pr = 1.0f / f[k];
                #pragma unroll
                for (int i = 0; i < PP; ++i) {
                    if (i != k) {
                        const float gg = f[i] * pr;
                        colA[i] -= gg * colA[k];
                        colB[i] -= gg * colB[k];
                    }
                }
                colA[k] *= pr; colB[k] *= pr;
            }
            if (lane >= PP) {
                #pragma unroll
                for (int i = 0; i < PP; ++i) sK[lane - PP][i] = colA[i];
            } else {
                #pragma unroll
                for (int i = 0; i < PP; ++i) sK[PP + lane][i] = colB[i];
            }
        } else if (t + 1 < TT) {
            const int wt = tid - 32;
            const float* An = Ab + (size_t)(t + 1) * NN * NN;
            const float* Cn = Cb + (size_t)(t + 1) * PP * NN;
            const float* Bn = Bb + (size_t)(t + 1) * NN * MM;
            for (int idx = wt; idx < NN * NN; idx += 480) sA[idx >> 5][idx & 31] = An[idx];
            for (int idx = wt; idx < PP * NN; idx += 480) sC[idx >> 5][idx & 31] = Cn[idx];
            for (int idx = wt; idx < NN * MM; idx += 480) sB[idx >> 3][idx & 7] = Bn[idx];
            if (wt < PP) sy[wt] = Yb[(t + 1) * PP + wt];
            else if (wt < PP + MM) su[wt - PP] = Ub[(t + 1) * MM + (wt - PP)];
        }
        __syncthreads();

        // ==== P5: Sig_f = Sigp - K@CS (algebraically symmetric); mu_f ====
        {
            const int i0 = wid, j = lane;
            float x0 = sSigp[i0][j], x1 = sSigp[i0 + 16][j];
            #pragma unroll
            for (int k = 0; k < PP; ++k) {
                const float c = sCS[k][j];
                x0 -= sK[i0][k] * c; x1 -= sK[i0 + 16][k] * c;
            }
            sSig[i0][j] = x0; sSig[i0 + 16][j] = x1;
            float* gf = &g_Sigf[b][t][0][0];
            gf[i0 * NN + j] = x0; gf[(i0 + 16) * NN + j] = x1;
        }
        if (tid < NN) {
            float m = smup[tid];
            #pragma unroll
            for (int k = 0; k < PP; ++k) m += sK[tid][k] * sr[k];
            smu[tid] = m;
            g_muf[b][t][tid] = m;
            g_mup[b][t][tid] = smup[tid];
        }
        __syncthreads();
    }
}

// ===== smoother gains + backward constants (fully parallel over b,t) =====
__global__ void __launch_bounds__(256) jgain_kernel(const float* __restrict__ A)
{
    const int t = blockIdx.x;     // 0..TT-2
    const int b = blockIdx.y;
    const int tid = threadIdx.x;
    const int tx = tid & 15, ty = tid >> 4;

    __shared__ float sSf[NN][NN + 1], sA[NN][NN + 1], sX[NN][NN + 1], sT2[NN][NN + 1];
    __shared__ float prow[2][2 * NN];
    __shared__ float sf[2][NN];
    __shared__ float smp1[NN];

    const float* Ab = A + ((size_t)b * TT + t) * NN * NN;
    for (int idx = tid; idx < NN * NN; idx += 256) {
        sSf[idx >> 5][idx & 31] = g_Sigf[b][t][idx >> 5][idx & 31];
        sA[idx >> 5][idx & 31]  = Ab[idx];
    }
    if (tid < NN) smp1[tid] = g_mup[b][t + 1][tid];
    __syncthreads();

    // X = Sigf @ A^T
    {
        float a00 = 0.f, a01 = 0.f, a10 = 0.f, a11 = 0.f;
        #pragma unroll
        for (int k = 0; k < NN; ++k) {
            const float l0 = sSf[ty][k], l1 = sSf[ty + 16][k];
            const float r0 = sA[tx][k],  r1 = sA[tx + 16][k];
            a00 += l0 * r0; a01 += l0 * r1; a10 += l1 * r0; a11 += l1 * r1;
        }
        sX[ty][tx] = a00;      sX[ty][tx + 16] = a01;
        sX[ty + 16][tx] = a10; sX[ty + 16][tx + 16] = a11;
    }
    __syncthreads();

    // Gauss-Jordan on [Sigp_{t+1} | X^T]; thread owns 8 cols of one row in regs
    const int row = tid >> 3;
    const int c0  = (tid & 7) * 8;
    float r8[8];
    if (c0 < NN) {
        #pragma unroll
        for (int m = 0; m < 8; ++m) r8[m] = g_Sigp[b][t + 1][row][c0 + m];
    } else {
        #pragma unroll
        for (int m = 0; m < 8; ++m) r8[m] = sX[c0 - NN + m][row];   // X^T
    }
    #pragma unroll
    for (int k = 0; k < NN; ++k) {
        const int pb = k & 1;
        if (row == k) {
            #pragma unroll
            for (int m = 0; m < 8; ++m) prow[pb][c0 + m] = r8[m];
        }
        if ((tid & 7) == (k >> 3)) sf[pb][row] = r8[k & 7];
        __syncthreads();
        const float pr = 1.0f / prow[pb][k];
        if (row == k) {
            #pragma unroll
            for (int m = 0; m < 8; ++m) r8[m] *= pr;
        } else {
            const float g = sf[pb][row] * pr;
            #pragma unroll
            for (int m = 0; m < 8; ++m) r8[m] -= g * prow[pb][c0 + m];
        }
    }
    __syncthreads();
    if (c0 >= NN) {
        #pragma unroll
        for (int m = 0; m < 8; ++m) sX[c0 - NN + m][row] = r8[m];   // J
    }
    __syncthreads();
    for (int idx = tid; idx < NN * NN; idx += 256) {
        g_J[b][t][idx >> 5][idx & 31] = sX[idx >> 5][idx & 31];
        sA[idx >> 5][idx & 31] = g_Sigp[b][t + 1][idx >> 5][idx & 31];
    }
    __syncthreads();

    // T2 = J @ Sigp_{t+1}
    {
        float a00 = 0.f, a01 = 0.f, a10 = 0.f, a11 = 0.f;
        #pragma unroll
        for (int k = 0; k < NN; ++k) {
            const float l0 = sX[ty][k], l1 = sX[ty + 16][k];
            const float r0 = sA[k][tx], r1 = sA[k][tx + 16];
            a00 += l0 * r0; a01 += l0 * r1; a10 += l1 * r0; a11 += l1 * r1;
        }
        sT2[ty][tx] = a00;      sT2[ty][tx + 16] = a01;
        sT2[ty + 16][tx] = a10; sT2[ty + 16][tx + 16] = a11;
    }
    __syncthreads();

    // G = Sf - T2 @ J^T (symmetric up to fp) ; mb = muf - J mp1
    {
        float e00 = 0.f, e01 = 0.f, e10 = 0.f, e11 = 0.f;
        #pragma unroll
        for (int k = 0; k < NN; ++k) {
            const float t0 = sT2[ty][k], t1 = sT2[ty + 16][k];
            const float j0 = sX[tx][k],  j1 = sX[tx + 16][k];
            e00 += t0 * j0; e01 += t0 * j1; e10 += t1 * j0; e11 += t1 * j1;
        }
        float* gg = &g_G[b][t][0][0];
        gg[ty * NN + tx]             = sSf[ty][tx]           - e00;
        gg[ty * NN + tx + 16]        = sSf[ty][tx + 16]      - e01;
        gg[(ty + 16) * NN + tx]      = sSf[ty + 16][tx]      - e10;
        gg[(ty + 16) * NN + tx + 16] = sSf[ty + 16][tx + 16] - e11;
    }
    if (tid < NN) {
        float m = g_muf[b][t][tid];
        #pragma unroll
        for (int k = 0; k < NN; ++k) m -= sX[tid][k] * smp1[k];
        g_mb[b][t][tid] = m;
    }
}

// ========== backward RTS: Sig_s = G + J Sig_s J^T ; mu = mb + J mu ==========
__global__ void __launch_bounds__(512) bwd_kernel(float* __restrict__ out)
{
    const int b = blockIdx.x;
    const int tid = threadIdx.x;
    const int j  = tid & 31;
    const int i0 = tid >> 5;

    __shared__ float sJ[2][NN][NN + 1], sTmp[NN][NN + 1], sSig[NN][NN + 1];
    __shared__ float smu[NN];

    {
        const float v0 = g_Sigf[b][TT - 1][i0][j];
        const float v1 = g_Sigf[b][TT - 1][i0 + 16][j];
        sSig[i0][j] = v0; sSig[i0 + 16][j] = v1;
        const size_t base = ((size_t)b * TT + (TT - 1)) * NN;
        out[(base + i0) * NP1 + 1 + j] = v0;
        out[(base + i0 + 16) * NP1 + 1 + j] = v1;
        if (tid < NN) {
            const float m = g_muf[b][TT - 1][tid];
            smu[tid] = m;
            out[(base + tid) * NP1] = m;
        }
    }
    float pG0 = g_G[b][TT - 2][i0][j];
    float pG1 = g_G[b][TT - 2][i0 + 16][j];
    sJ[0][i0][j]      = g_J[b][TT - 2][i0][j];
    sJ[0][i0 + 16][j] = g_J[b][TT - 2][i0 + 16][j];
    __syncthreads();

    int cur = 0;
    for (int t = TT - 2; t >= 0; --t) {
        // phase 1: tmp = J @ Sig_s ; mu (regs) ; prefetch t-1
        float a0 = 0.f, a1 = 0.f;
        #pragma unroll
        for (int k = 0; k < NN; ++k) {
            const float r = sSig[k][j];
            a0 += sJ[cur][i0][k] * r; a1 += sJ[cur][i0 + 16][k] * r;
        }
        sTmp[i0][j] = a0; sTmp[i0 + 16][j] = a1;

        float m = 0.f;
        if (tid < NN) {
            m = g_mb[b][t][tid];
            #pragma unroll
            for (int k = 0; k < NN; ++k) m += sJ[cur][tid][k] * smu[k];
        }
        float nJ0 = 0.f, nJ1 = 0.f, nG0 = 0.f, nG1 = 0.f;
        if (t > 0) {
            nJ0 = g_J[b][t - 1][i0][j];     nJ1 = g_J[b][t - 1][i0 + 16][j];
            nG0 = g_G[b][t - 1][i0][j];     nG1 = g_G[b][t - 1][i0 + 16][j];
        }
        __syncthreads();

        // phase 2: Sig_s = G + tmp @ J^T (symmetric up to fp) ; emit
        {
            float e0 = 0.f, e1 = 0.f;
            #pragma unroll
            for (int k = 0; k < NN; ++k) {
                const float jj = sJ[cur][j][k];
                e0 += sTmp[i0][k] * jj; e1 += sTmp[i0 + 16][k] * jj;
            }
            const float v0 = pG0 + e0;
            const float v1 = pG1 + e1;
            sSig[i0][j] = v0; sSig[i0 + 16][j] = v1;
            const size_t base = ((size_t)b * TT + t) * NN;
            out[(base + i0) * NP1 + 1 + j] = v0;
            out[(base + i0 + 16) * NP1 + 1 + j] = v1;
            if (tid < NN) {
                smu[tid] = m;
                out[(base + tid) * NP1] = m;
            }
        }
        if (t > 0) {
            sJ[cur ^ 1][i0][j] = nJ0; sJ[cur ^ 1][i0 + 16][j] = nJ1;
            pG0 = nG0; pG1 = nG1;
        }
        __syncthreads();
        cur ^= 1;
    }
}

// ---------------- launch ----------------
extern "C" void kernel_launch(void* const* d_in, const int* in_sizes, int n_in,
                              void* d_out, int out_size)
{
    const float* Y      = (const float*)d_in[0];
    const float* U      = (const float*)d_in[1];
    const float* A      = (const float*)d_in[2];
    const float* Bm     = (const float*)d_in[3];
    const float* C      = (const float*)d_in[4];
    const float* mu0    = (const float*)d_in[5];
    const float* Sigma0 = (const float*)d_in[6];
    float* out = (float*)d_out;

    fwd_kernel<<<BB, 512>>>(Y, U, A, Bm, C, mu0, Sigma0);
    jgain_kernel<<<dim3(TT - 1, BB), 256>>>(A);
    bwd_kernel<<<BB, 512>>>(out);
}